// round 13
// baseline (speedup 1.0000x reference)
#include <cuda_runtime.h>
#include <cstdint>

#define BATCH 2
#define SEQ   2048
#define NHEAD 12
#define HSZ   64
#define HID   768
#define M_TOK (BATCH*SEQ)
#define QKV_N (3*HID)

__device__ float g_qkv[M_TOK * QKV_N];
__device__ float g_ctx[M_TOK * HID];
__device__ float g_hs [M_TOK * HID];
__device__ float g_w1 [HID * QKV_N];
__device__ float g_w2 [HID * HID];

// ===========================================================================
__device__ __forceinline__ float to_tf32(float x) {
    uint32_t u;
    asm("cvt.rna.tf32.f32 %0, %1;" : "=r"(u) : "f"(x));
    return __uint_as_float(u);
}
__device__ __forceinline__ float4 cvt4(float4 v) {
    float4 r;
    r.x = to_tf32(v.x); r.y = to_tf32(v.y);
    r.z = to_tf32(v.z); r.w = to_tf32(v.w);
    return r;
}
__device__ __forceinline__ void mma_tf32(float* d, const float* a, const float* b) {
    asm volatile(
        "mma.sync.aligned.m16n8k8.row.col.f32.tf32.tf32.f32 "
        "{%0,%1,%2,%3}, {%4,%5,%6,%7}, {%8,%9}, {%0,%1,%2,%3};"
        : "+f"(d[0]), "+f"(d[1]), "+f"(d[2]), "+f"(d[3])
        : "r"(__float_as_uint(a[0])), "r"(__float_as_uint(a[1])),
          "r"(__float_as_uint(a[2])), "r"(__float_as_uint(a[3])),
          "r"(__float_as_uint(b[0])), "r"(__float_as_uint(b[1])));
}
__device__ __forceinline__ uint32_t smem_u32(const void* p) {
    uint32_t a;
    asm("{ .reg .u64 t; cvta.to.shared.u64 t, %1; cvt.u32.u64 %0, t; }"
        : "=r"(a) : "l"(p));
    return a;
}
__device__ __forceinline__ void cp16(uint32_t dst, const void* src) {
    asm volatile("cp.async.cg.shared.global [%0], [%1], 16;"
                 :: "r"(dst), "l"(src));
}
__device__ __forceinline__ void cp_commit() {
    asm volatile("cp.async.commit_group;" ::: "memory");
}
template<int N> __device__ __forceinline__ void cp_wait() {
    asm volatile("cp.async.wait_group %0;" :: "n"(N) : "memory");
}

// ===========================================================================
// Pre-round all three inputs in one launch
// ===========================================================================
#define N4_HS (M_TOK*HID/4)
#define N4_W1 (HID*QKV_N/4)
#define N4_W2 (HID*HID/4)

__global__ void round_all(const float4* __restrict__ hs, float4* __restrict__ hsr,
                          const float4* __restrict__ w1, float4* __restrict__ w1r,
                          const float4* __restrict__ w2, float4* __restrict__ w2r) {
    int i = blockIdx.x * 256 + threadIdx.x;
    if (i < N4_HS) hsr[i] = cvt4(hs[i]);
    if (i < N4_W1) w1r[i] = cvt4(w1[i]);
    if (i < N4_W2) w2r[i] = cvt4(w2[i]);
}

// ===========================================================================
// GEMM: BMx128 block, 8 warps (2x4), warp tile (BM/2)x32, BK=16,
// 3-stage cp.async, one barrier per stage. MINB = min blocks/SM.
// ===========================================================================
#define APIT 20
#define BPIT 136
#define BSTG (16*BPIT)

template<int BM, bool ROUND_OUT, int MINB>
__global__ void __launch_bounds__(256, MINB)
gemm_tc(const float* __restrict__ A, const float* __restrict__ B,
        const float* __restrict__ bias, float* __restrict__ C,
        int M, int N, int K) {
    constexpr int ASTG = BM * APIT;
    constexpr int STG  = ASTG + BSTG;
    constexpr int MF   = BM / 32;
    constexpr int NCHA = BM / 64;

    extern __shared__ float sm[];
    const uint32_t smb = smem_u32(sm);

    const int tid = threadIdx.x, lane = tid & 31, wid = tid >> 5;
    const int g = lane >> 2, q = lane & 3;
    const int wm = wid >> 2, wn = wid & 3;
    const int bm = blockIdx.y * BM, bn = blockIdx.x * 128;
    const int nst = K / 16;

    auto prefetch = [&](int S) {
        const int k0 = S * 16;
        const uint32_t bs = smb + (S % 3) * (STG * 4);
#pragma unroll
        for (int r = 0; r < NCHA; ++r) {
            const int c = tid + 256 * r;
            const int row = c >> 2, kc = c & 3;
            cp16(bs + (row * APIT + kc * 4) * 4,
                 A + (size_t)(bm + row) * K + k0 + kc * 4);
        }
#pragma unroll
        for (int r = 0; r < 2; ++r) {
            const int c = tid + 256 * r;
            const int row = c >> 5, nc = c & 31;
            cp16(bs + (ASTG + row * BPIT + nc * 4) * 4,
                 B + (size_t)(k0 + row) * N + bn + nc * 4);
        }
    };

    float acc[MF][4][4];
#pragma unroll
    for (int mf = 0; mf < MF; ++mf)
#pragma unroll
        for (int nf = 0; nf < 4; ++nf)
#pragma unroll
            for (int e = 0; e < 4; ++e) acc[mf][nf][e] = 0.f;

    prefetch(0); cp_commit();
    prefetch(1); cp_commit();

    for (int s = 0; s < nst; ++s) {
        if (s + 1 < nst) cp_wait<1>(); else cp_wait<0>();
        __syncthreads();
        if (s + 2 < nst) { prefetch(s + 2); cp_commit(); }

        const float* a  = sm + (s % 3) * STG;
        const float* bb = a + ASTG;
#pragma unroll
        for (int ks = 0; ks < 2; ++ks) {
            const int k0 = ks * 8;
            float af[MF][4];
#pragma unroll
            for (int mf = 0; mf < MF; ++mf) {
                const int r0 = (wm * (BM / 2) + mf * 16 + g) * APIT + k0 + q;
                af[mf][0] = a[r0];
                af[mf][1] = a[r0 + 8 * APIT];
                af[mf][2] = a[r0 + 4];
                af[mf][3] = a[r0 + 8 * APIT + 4];
            }
#pragma unroll
            for (int nf = 0; nf < 4; ++nf) {
                float bf[2];
                const int c = wn * 32 + nf * 8 + g;
                bf[0] = bb[(k0 + q) * BPIT + c];
                bf[1] = bb[(k0 + q + 4) * BPIT + c];
#pragma unroll
                for (int mf = 0; mf < MF; ++mf)
                    mma_tf32(acc[mf][nf], af[mf], bf);
            }
        }
    }

#pragma unroll
    for (int mf = 0; mf < MF; ++mf) {
        const int row = bm + wm * (BM / 2) + mf * 16 + g;
#pragma unroll
        for (int nf = 0; nf < 4; ++nf) {
            const int col = bn + wn * 32 + nf * 8 + 2 * q;
            float2 bv = *(const float2*)(bias + col);
            float2 v0 = { acc[mf][nf][0] + bv.x, acc[mf][nf][1] + bv.y };
            float2 v1 = { acc[mf][nf][2] + bv.x, acc[mf][nf][3] + bv.y };
            if (ROUND_OUT) {
                v0.x = to_tf32(v0.x); v0.y = to_tf32(v0.y);
                v1.x = to_tf32(v1.x); v1.y = to_tf32(v1.y);
            }
            *(float2*)(C + (size_t)row * N + col) = v0;
            *(float2*)(C + (size_t)(row + 8) * N + col) = v1;
        }
    }
}

#define GEMM_SMEM_BM(BM) (3 * ((BM) * APIT + BSTG) * 4)

// ===========================================================================
// Attention: R11 structure; P written into the SPENT K buffer (one extra
// barrier after softmax) -> smem 71680B -> 3 CTAs/SM.
// Q staged via K0 buffer before first prefetch.
// ===========================================================================
#define KP 68
#define VP 72
#define KSTG (64*KP)
#define VSTG (64*VP)
#define ATTN_SMEM ((2*KSTG + 2*VSTG)*4)   // 71680 B

__global__ void __launch_bounds__(128, 3)
attn_tc(const float* __restrict__ qkv, float* __restrict__ ctx) {
    const int qt = blockIdx.x, h = blockIdx.y, b = blockIdx.z;
    const int tid = threadIdx.x, lane = tid & 31, wid = tid >> 5;
    const int g = lane >> 2, q = lane & 3;

    extern __shared__ float sms[];
    const uint32_t smb = smem_u32(sms);

#define KV_PREFETCH(KT, P)                                                      \
    do {                                                                        \
        const float* _kb = qkv + (size_t)(b * SEQ + (KT) * 64) * QKV_N          \
                           + HID + h * HSZ;                                     \
        const uint32_t _kbs = smb + (P) * (KSTG * 4);                           \
        const uint32_t _vbs = smb + (2 * KSTG + (P) * VSTG) * 4;                \
        _Pragma("unroll")                                                       \
        for (int _r = 0; _r < 8; ++_r) {                                        \
            const int _c = tid + 128 * _r;                                      \
            const int _row = _c >> 4, _kc = _c & 15;                            \
            cp16(_kbs + (_row * KP + _kc * 4) * 4,                              \
                 _kb + (size_t)_row * QKV_N + _kc * 4);                         \
            cp16(_vbs + (_row * VP + _kc * 4) * 4,                              \
                 _kb + HID + (size_t)_row * QKV_N + _kc * 4);                   \
        }                                                                       \
    } while (0)

    // ---- stage Q into K0 buffer, pull fragments, release buffer ----
    {
        const float* qb = qkv + (size_t)(b * SEQ + qt * 64) * QKV_N + h * HSZ;
#pragma unroll
        for (int r = 0; r < 8; ++r) {
            const int c = tid + 128 * r;
            const int row = c >> 4, kc = c & 15;
            cp16(smb + (row * KP + kc * 4) * 4, qb + (size_t)row * QKV_N + kc * 4);
        }
        cp_commit();
        cp_wait<0>();
    }
    __syncthreads();

    float qa[8][4];
#pragma unroll
    for (int ks = 0; ks < 8; ++ks) {
        const int r0 = (wid * 16 + g) * KP + ks * 8 + q;
        qa[ks][0] = sms[r0] * 0.125f;
        qa[ks][1] = sms[r0 + 8 * KP] * 0.125f;
        qa[ks][2] = sms[r0 + 4] * 0.125f;
        qa[ks][3] = sms[r0 + 8 * KP + 4] * 0.125f;
    }
    __syncthreads();   // all Q reads done before K0 is overwritten

    KV_PREFETCH(0, 0); cp_commit();

    float o[8][4];
#pragma unroll
    for (int nf = 0; nf < 8; ++nf)
#pragma unroll
        for (int e = 0; e < 4; ++e) o[nf][e] = 0.f;
    float m0 = -1e30f, m1 = -1e30f, l0 = 0.f, l1 = 0.f;

    for (int kt = 0; kt <= qt; ++kt) {
        const int p = kt & 1;
        cp_wait<0>();        // KV(kt) complete
        __syncthreads();     // all warps done with buffers of iter kt-1
        if (kt < qt) {
            KV_PREFETCH(kt + 1, 1 - p);
            cp_commit();
        }

        const float* Ks = sms + p * KSTG;
        const float* Vs = sms + 2 * KSTG + p * VSTG;
        float* Pw = sms + p * KSTG + wid * 16 * KP;   // spent-K reuse
        const int nlim = (kt == qt) ? (2 * wid + 2) : 8;

        // ---- S = Q @ K^T ----
        float s[8][4];
        for (int nf = 0; nf < nlim; ++nf) {
            s[nf][0] = 0.f; s[nf][1] = 0.f; s[nf][2] = 0.f; s[nf][3] = 0.f;
            const int nrow = (nf * 8 + g) * KP;
#pragma unroll
            for (int ks = 0; ks < 8; ++ks) {
                float bf[2];
                bf[0] = Ks[nrow + ks * 8 + q];
                bf[1] = Ks[nrow + ks * 8 + q + 4];
                mma_tf32(s[nf], qa[ks], bf);
            }
        }

        if (kt == qt) {
            const int q0 = wid * 16 + g;
            for (int nf = 0; nf < nlim; ++nf) {
                const int key = nf * 8 + 2 * q;
                if (key     > q0)     s[nf][0] = -1e30f;
                if (key + 1 > q0)     s[nf][1] = -1e30f;
                if (key     > q0 + 8) s[nf][2] = -1e30f;
                if (key + 1 > q0 + 8) s[nf][3] = -1e30f;
            }
        }

        // ---- online softmax ----
        float mx0 = -1e30f, mx1 = -1e30f;
        for (int nf = 0; nf < nlim; ++nf) {
            mx0 = fmaxf(mx0, fmaxf(s[nf][0], s[nf][1]));
            mx1 = fmaxf(mx1, fmaxf(s[nf][2], s[nf][3]));
        }
        mx0 = fmaxf(mx0, __shfl_xor_sync(0xffffffffu, mx0, 1));
        mx0 = fmaxf(mx0, __shfl_xor_sync(0xffffffffu, mx0, 2));
        mx1 = fmaxf(mx1, __shfl_xor_sync(0xffffffffu, mx1, 1));
        mx1 = fmaxf(mx1, __shfl_xor_sync(0xffffffffu, mx1, 2));
        const float mn0 = fmaxf(m0, mx0), mn1 = fmaxf(m1, mx1);
        const float a0 = __expf(m0 - mn0), a1 = __expf(m1 - mn1);
        m0 = mn0; m1 = mn1;

        float sum0 = 0.f, sum1 = 0.f;
        for (int nf = 0; nf < nlim; ++nf) {
            s[nf][0] = __expf(s[nf][0] - mn0);
            s[nf][1] = __expf(s[nf][1] - mn0);
            s[nf][2] = __expf(s[nf][2] - mn1);
            s[nf][3] = __expf(s[nf][3] - mn1);
            sum0 += s[nf][0] + s[nf][1];
            sum1 += s[nf][2] + s[nf][3];
        }
        sum0 += __shfl_xor_sync(0xffffffffu, sum0, 1);
        sum0 += __shfl_xor_sync(0xffffffffu, sum0, 2);
        sum1 += __shfl_xor_sync(0xffffffffu, sum1, 1);
        sum1 += __shfl_xor_sync(0xffffffffu, sum1, 2);
        l0 = l0 * a0 + sum0;
        l1 = l1 * a1 + sum1;
#pragma unroll
        for (int nf = 0; nf < 8; ++nf) {
            o[nf][0] *= a0; o[nf][1] *= a0;
            o[nf][2] *= a1; o[nf][3] *= a1;
        }

        __syncthreads();   // ALL warps finished reading Ks(p) -> safe to write P
        for (int nf = 0; nf < nlim; ++nf) {
            const int c = nf * 8 + 2 * q;
            float2 w0 = { to_tf32(s[nf][0]), to_tf32(s[nf][1]) };
            float2 w1 = { to_tf32(s[nf][2]), to_tf32(s[nf][3]) };
            *(float2*)&Pw[g * KP + c] = w0;
            *(float2*)&Pw[(g + 8) * KP + c] = w1;
        }
        __syncwarp();

        // ---- O += P @ V ----
        for (int ks = 0; ks < nlim; ++ks) {
            float pf[4];
            const int pr = g * KP + ks * 8 + q;
            pf[0] = Pw[pr];
            pf[1] = Pw[pr + 8 * KP];
            pf[2] = Pw[pr + 4];
            pf[3] = Pw[pr + 8 * KP + 4];
#pragma unroll
            for (int nf = 0; nf < 8; ++nf) {
                float bf[2];
                bf[0] = Vs[(ks * 8 + q) * VP + nf * 8 + g];
                bf[1] = Vs[(ks * 8 + q + 4) * VP + nf * 8 + g];
                mma_tf32(o[nf], pf, bf);
            }
        }
        // next iteration's leading sync orders buffer reuse
    }

    const float inv0 = 1.0f / l0, inv1 = 1.0f / l1;
    float* ob = ctx + (size_t)(b * SEQ + qt * 64 + wid * 16 + g) * HID + h * HSZ;
#pragma unroll
    for (int nf = 0; nf < 8; ++nf) {
        const int c = nf * 8 + 2 * q;
        float2 v0 = { to_tf32(o[nf][0] * inv0), to_tf32(o[nf][1] * inv0) };
        float2 v1 = { to_tf32(o[nf][2] * inv1), to_tf32(o[nf][3] * inv1) };
        *(float2*)(ob + c) = v0;
        *(float2*)(ob + (size_t)8 * HID + c) = v1;
    }
}

// ===========================================================================
extern "C" void kernel_launch(void* const* d_in, const int* in_sizes, int n_in,
                              void* d_out, int out_size) {
    const float* hs = (const float*)d_in[0];
    const float* w1 = (const float*)d_in[1];
    const float* b1 = (const float*)d_in[2];
    const float* w2 = (const float*)d_in[3];
    const float* b2 = (const float*)d_in[4];
    float* out = (float*)d_out;

    float *qkv, *ctx, *hsr, *w1r, *w2r;
    cudaGetSymbolAddress((void**)&qkv, g_qkv);
    cudaGetSymbolAddress((void**)&ctx, g_ctx);
    cudaGetSymbolAddress((void**)&hsr, g_hs);
    cudaGetSymbolAddress((void**)&w1r, g_w1);
    cudaGetSymbolAddress((void**)&w2r, g_w2);

    cudaFuncSetAttribute((const void*)gemm_tc<128, true, 2>,
                         cudaFuncAttributeMaxDynamicSharedMemorySize,
                         GEMM_SMEM_BM(128));
    cudaFuncSetAttribute((const void*)gemm_tc<64, false, 3>,
                         cudaFuncAttributeMaxDynamicSharedMemorySize,
                         GEMM_SMEM_BM(64));
    cudaFuncSetAttribute((const void*)attn_tc,
                         cudaFuncAttributeMaxDynamicSharedMemorySize, ATTN_SMEM);

    round_all<<<(N4_HS + 255) / 256, 256>>>(
        (const float4*)hs, (float4*)hsr,
        (const float4*)w1, (float4*)w1r,
        (const float4*)w2, (float4*)w2r);

    gemm_tc<128, true, 2><<<dim3(QKV_N / 128, M_TOK / 128), 256,
                            GEMM_SMEM_BM(128)>>>(
        hsr, w1r, b1, qkv, M_TOK, QKV_N, HID);

    attn_tc<<<dim3(SEQ / 64, NHEAD, BATCH), 128, ATTN_SMEM>>>(qkv, ctx);

    gemm_tc<64, false, 3><<<dim3(HID / 128, M_TOK / 64), 256,
                            GEMM_SMEM_BM(64)>>>(
        ctx, w2r, b2, out, M_TOK, HID, HID);
}

// round 14
// speedup vs baseline: 1.0714x; 1.0714x over previous
#include <cuda_runtime.h>
#include <cstdint>

#define BATCH 2
#define SEQ   2048
#define NHEAD 12
#define HSZ   64
#define HID   768
#define M_TOK (BATCH*SEQ)
#define QKV_N (3*HID)

__device__ float g_qkv[M_TOK * QKV_N];
__device__ float g_ctx[M_TOK * HID];
__device__ float g_hs [M_TOK * HID];
__device__ float g_w1 [HID * QKV_N];
__device__ float g_w2 [HID * HID];

// ===========================================================================
__device__ __forceinline__ float to_tf32(float x) {
    uint32_t u;
    asm("cvt.rna.tf32.f32 %0, %1;" : "=r"(u) : "f"(x));
    return __uint_as_float(u);
}
__device__ __forceinline__ float4 cvt4(float4 v) {
    float4 r;
    r.x = to_tf32(v.x); r.y = to_tf32(v.y);
    r.z = to_tf32(v.z); r.w = to_tf32(v.w);
    return r;
}
__device__ __forceinline__ void mma_tf32(float* d, const float* a, const float* b) {
    asm volatile(
        "mma.sync.aligned.m16n8k8.row.col.f32.tf32.tf32.f32 "
        "{%0,%1,%2,%3}, {%4,%5,%6,%7}, {%8,%9}, {%0,%1,%2,%3};"
        : "+f"(d[0]), "+f"(d[1]), "+f"(d[2]), "+f"(d[3])
        : "r"(__float_as_uint(a[0])), "r"(__float_as_uint(a[1])),
          "r"(__float_as_uint(a[2])), "r"(__float_as_uint(a[3])),
          "r"(__float_as_uint(b[0])), "r"(__float_as_uint(b[1])));
}
__device__ __forceinline__ uint32_t smem_u32(const void* p) {
    uint32_t a;
    asm("{ .reg .u64 t; cvta.to.shared.u64 t, %1; cvt.u32.u64 %0, t; }"
        : "=r"(a) : "l"(p));
    return a;
}
__device__ __forceinline__ void cp16(uint32_t dst, const void* src) {
    asm volatile("cp.async.cg.shared.global [%0], [%1], 16;"
                 :: "r"(dst), "l"(src));
}
__device__ __forceinline__ void cp_commit() {
    asm volatile("cp.async.commit_group;" ::: "memory");
}
template<int N> __device__ __forceinline__ void cp_wait() {
    asm volatile("cp.async.wait_group %0;" :: "n"(N) : "memory");
}

// ===========================================================================
// Pre-round all three inputs in one launch
// ===========================================================================
#define N4_HS (M_TOK*HID/4)
#define N4_W1 (HID*QKV_N/4)
#define N4_W2 (HID*HID/4)

__global__ void round_all(const float4* __restrict__ hs, float4* __restrict__ hsr,
                          const float4* __restrict__ w1, float4* __restrict__ w1r,
                          const float4* __restrict__ w2, float4* __restrict__ w2r) {
    int i = blockIdx.x * 256 + threadIdx.x;
    if (i < N4_HS) hsr[i] = cvt4(hs[i]);
    if (i < N4_W1) w1r[i] = cvt4(w1[i]);
    if (i < N4_W2) w2r[i] = cvt4(w2[i]);
}

// ===========================================================================
// GEMM: BMx128 block, 8 warps (2x4), warp tile (BM/2)x32, BK=16,
// 3-stage cp.async, one barrier per stage. MINB = min blocks/SM.
// ===========================================================================
#define APIT 20
#define BPIT 136
#define BSTG (16*BPIT)

template<int BM, bool ROUND_OUT, int MINB>
__global__ void __launch_bounds__(256, MINB)
gemm_tc(const float* __restrict__ A, const float* __restrict__ B,
        const float* __restrict__ bias, float* __restrict__ C,
        int M, int N, int K) {
    constexpr int ASTG = BM * APIT;
    constexpr int STG  = ASTG + BSTG;
    constexpr int MF   = BM / 32;
    constexpr int NCHA = BM / 64;

    extern __shared__ float sm[];
    const uint32_t smb = smem_u32(sm);

    const int tid = threadIdx.x, lane = tid & 31, wid = tid >> 5;
    const int g = lane >> 2, q = lane & 3;
    const int wm = wid >> 2, wn = wid & 3;
    const int bm = blockIdx.y * BM, bn = blockIdx.x * 128;
    const int nst = K / 16;

    auto prefetch = [&](int S) {
        const int k0 = S * 16;
        const uint32_t bs = smb + (S % 3) * (STG * 4);
#pragma unroll
        for (int r = 0; r < NCHA; ++r) {
            const int c = tid + 256 * r;
            const int row = c >> 2, kc = c & 3;
            cp16(bs + (row * APIT + kc * 4) * 4,
                 A + (size_t)(bm + row) * K + k0 + kc * 4);
        }
#pragma unroll
        for (int r = 0; r < 2; ++r) {
            const int c = tid + 256 * r;
            const int row = c >> 5, nc = c & 31;
            cp16(bs + (ASTG + row * BPIT + nc * 4) * 4,
                 B + (size_t)(k0 + row) * N + bn + nc * 4);
        }
    };

    float acc[MF][4][4];
#pragma unroll
    for (int mf = 0; mf < MF; ++mf)
#pragma unroll
        for (int nf = 0; nf < 4; ++nf)
#pragma unroll
            for (int e = 0; e < 4; ++e) acc[mf][nf][e] = 0.f;

    prefetch(0); cp_commit();
    prefetch(1); cp_commit();

    for (int s = 0; s < nst; ++s) {
        if (s + 1 < nst) cp_wait<1>(); else cp_wait<0>();
        __syncthreads();
        if (s + 2 < nst) { prefetch(s + 2); cp_commit(); }

        const float* a  = sm + (s % 3) * STG;
        const float* bb = a + ASTG;
#pragma unroll
        for (int ks = 0; ks < 2; ++ks) {
            const int k0 = ks * 8;
            float af[MF][4];
#pragma unroll
            for (int mf = 0; mf < MF; ++mf) {
                const int r0 = (wm * (BM / 2) + mf * 16 + g) * APIT + k0 + q;
                af[mf][0] = a[r0];
                af[mf][1] = a[r0 + 8 * APIT];
                af[mf][2] = a[r0 + 4];
                af[mf][3] = a[r0 + 8 * APIT + 4];
            }
#pragma unroll
            for (int nf = 0; nf < 4; ++nf) {
                float bf[2];
                const int c = wn * 32 + nf * 8 + g;
                bf[0] = bb[(k0 + q) * BPIT + c];
                bf[1] = bb[(k0 + q + 4) * BPIT + c];
#pragma unroll
                for (int mf = 0; mf < MF; ++mf)
                    mma_tf32(acc[mf][nf], af[mf], bf);
            }
        }
    }

#pragma unroll
    for (int mf = 0; mf < MF; ++mf) {
        const int row = bm + wm * (BM / 2) + mf * 16 + g;
#pragma unroll
        for (int nf = 0; nf < 4; ++nf) {
            const int col = bn + wn * 32 + nf * 8 + 2 * q;
            float2 bv = *(const float2*)(bias + col);
            float2 v0 = { acc[mf][nf][0] + bv.x, acc[mf][nf][1] + bv.y };
            float2 v1 = { acc[mf][nf][2] + bv.x, acc[mf][nf][3] + bv.y };
            if (ROUND_OUT) {
                v0.x = to_tf32(v0.x); v0.y = to_tf32(v0.y);
                v1.x = to_tf32(v1.x); v1.y = to_tf32(v1.y);
            }
            *(float2*)(C + (size_t)row * N + col) = v0;
            *(float2*)(C + (size_t)(row + 8) * N + col) = v1;
        }
    }
}

#define GEMM_SMEM_BM(BM) (3 * ((BM) * APIT + BSTG) * 4)

// ===========================================================================
// Attention: R12 version verbatim (best measured, ~190us). 128 threads,
// KV tiles 64, double-buffered cp.async, one barrier per tile, Q/P region.
// ===========================================================================
#define KP 68
#define VP 72
#define KSTG (64*KP)
#define VSTG (64*VP)
#define PQ_OFF (2*KSTG + 2*VSTG)
#define ATTN_SMEM ((PQ_OFF + 4352)*4)   // 89088 B

__global__ void __launch_bounds__(128)
attn_tc(const float* __restrict__ qkv, float* __restrict__ ctx) {
    const int qt = blockIdx.x, h = blockIdx.y, b = blockIdx.z;
    const int tid = threadIdx.x, lane = tid & 31, wid = tid >> 5;
    const int g = lane >> 2, q = lane & 3;

    extern __shared__ float sms[];
    const uint32_t smb = smem_u32(sms);
    float* PQ = sms + PQ_OFF;
    float* Pw = PQ + wid * 16 * KP;

#define KV_PREFETCH(KT, P)                                                      \
    do {                                                                        \
        const float* _kb = qkv + (size_t)(b * SEQ + (KT) * 64) * QKV_N          \
                           + HID + h * HSZ;                                     \
        const uint32_t _kbs = smb + (P) * (KSTG * 4);                           \
        const uint32_t _vbs = smb + (2 * KSTG + (P) * VSTG) * 4;                \
        _Pragma("unroll")                                                       \
        for (int _r = 0; _r < 8; ++_r) {                                        \
            const int _c = tid + 128 * _r;                                      \
            const int _row = _c >> 4, _kc = _c & 15;                            \
            cp16(_kbs + (_row * KP + _kc * 4) * 4,                              \
                 _kb + (size_t)_row * QKV_N + _kc * 4);                         \
            cp16(_vbs + (_row * VP + _kc * 4) * 4,                              \
                 _kb + HID + (size_t)_row * QKV_N + _kc * 4);                   \
        }                                                                       \
    } while (0)

    {
        const float* qb = qkv + (size_t)(b * SEQ + qt * 64) * QKV_N + h * HSZ;
        const uint32_t pqb = smb + PQ_OFF * 4;
#pragma unroll
        for (int r = 0; r < 8; ++r) {
            const int c = tid + 128 * r;
            const int row = c >> 4, kc = c & 15;
            cp16(pqb + (row * KP + kc * 4) * 4, qb + (size_t)row * QKV_N + kc * 4);
        }
        cp_commit();
    }
    KV_PREFETCH(0, 0); cp_commit();
    cp_wait<1>();
    __syncthreads();

    float qa[8][4];
#pragma unroll
    for (int ks = 0; ks < 8; ++ks) {
        const int r0 = (wid * 16 + g) * KP + ks * 8 + q;
        qa[ks][0] = PQ[r0] * 0.125f;
        qa[ks][1] = PQ[r0 + 8 * KP] * 0.125f;
        qa[ks][2] = PQ[r0 + 4] * 0.125f;
        qa[ks][3] = PQ[r0 + 8 * KP + 4] * 0.125f;
    }

    float o[8][4];
#pragma unroll
    for (int nf = 0; nf < 8; ++nf)
#pragma unroll
        for (int e = 0; e < 4; ++e) o[nf][e] = 0.f;
    float m0 = -1e30f, m1 = -1e30f, l0 = 0.f, l1 = 0.f;

    for (int kt = 0; kt <= qt; ++kt) {
        const int p = kt & 1;
        cp_wait<0>();
        __syncthreads();
        if (kt < qt) {
            KV_PREFETCH(kt + 1, 1 - p);
            cp_commit();
        }

        const float* Ks = sms + p * KSTG;
        const float* Vs = sms + 2 * KSTG + p * VSTG;
        const int nlim = (kt == qt) ? (2 * wid + 2) : 8;

        float s[8][4];
        for (int nf = 0; nf < nlim; ++nf) {
            s[nf][0] = 0.f; s[nf][1] = 0.f; s[nf][2] = 0.f; s[nf][3] = 0.f;
            const int nrow = (nf * 8 + g) * KP;
#pragma unroll
            for (int ks = 0; ks < 8; ++ks) {
                float bf[2];
                bf[0] = Ks[nrow + ks * 8 + q];
                bf[1] = Ks[nrow + ks * 8 + q + 4];
                mma_tf32(s[nf], qa[ks], bf);
            }
        }

        if (kt == qt) {
            const int q0 = wid * 16 + g;
            for (int nf = 0; nf < nlim; ++nf) {
                const int key = nf * 8 + 2 * q;
                if (key     > q0)     s[nf][0] = -1e30f;
                if (key + 1 > q0)     s[nf][1] = -1e30f;
                if (key     > q0 + 8) s[nf][2] = -1e30f;
                if (key + 1 > q0 + 8) s[nf][3] = -1e30f;
            }
        }

        float mx0 = -1e30f, mx1 = -1e30f;
        for (int nf = 0; nf < nlim; ++nf) {
            mx0 = fmaxf(mx0, fmaxf(s[nf][0], s[nf][1]));
            mx1 = fmaxf(mx1, fmaxf(s[nf][2], s[nf][3]));
        }
        mx0 = fmaxf(mx0, __shfl_xor_sync(0xffffffffu, mx0, 1));
        mx0 = fmaxf(mx0, __shfl_xor_sync(0xffffffffu, mx0, 2));
        mx1 = fmaxf(mx1, __shfl_xor_sync(0xffffffffu, mx1, 1));
        mx1 = fmaxf(mx1, __shfl_xor_sync(0xffffffffu, mx1, 2));
        const float mn0 = fmaxf(m0, mx0), mn1 = fmaxf(m1, mx1);
        const float a0 = __expf(m0 - mn0), a1 = __expf(m1 - mn1);
        m0 = mn0; m1 = mn1;

        float sum0 = 0.f, sum1 = 0.f;
        for (int nf = 0; nf < nlim; ++nf) {
            s[nf][0] = __expf(s[nf][0] - mn0);
            s[nf][1] = __expf(s[nf][1] - mn0);
            s[nf][2] = __expf(s[nf][2] - mn1);
            s[nf][3] = __expf(s[nf][3] - mn1);
            sum0 += s[nf][0] + s[nf][1];
            sum1 += s[nf][2] + s[nf][3];
        }
        sum0 += __shfl_xor_sync(0xffffffffu, sum0, 1);
        sum0 += __shfl_xor_sync(0xffffffffu, sum0, 2);
        sum1 += __shfl_xor_sync(0xffffffffu, sum1, 1);
        sum1 += __shfl_xor_sync(0xffffffffu, sum1, 2);
        l0 = l0 * a0 + sum0;
        l1 = l1 * a1 + sum1;
#pragma unroll
        for (int nf = 0; nf < 8; ++nf) {
            o[nf][0] *= a0; o[nf][1] *= a0;
            o[nf][2] *= a1; o[nf][3] *= a1;
        }

        __syncwarp();
        for (int nf = 0; nf < nlim; ++nf) {
            const int c = nf * 8 + 2 * q;
            float2 w0 = { to_tf32(s[nf][0]), to_tf32(s[nf][1]) };
            float2 w1 = { to_tf32(s[nf][2]), to_tf32(s[nf][3]) };
            *(float2*)&Pw[g * KP + c] = w0;
            *(float2*)&Pw[(g + 8) * KP + c] = w1;
        }
        __syncwarp();

        for (int ks = 0; ks < nlim; ++ks) {
            float pf[4];
            const int pr = g * KP + ks * 8 + q;
            pf[0] = Pw[pr];
            pf[1] = Pw[pr + 8 * KP];
            pf[2] = Pw[pr + 4];
            pf[3] = Pw[pr + 8 * KP + 4];
#pragma unroll
            for (int nf = 0; nf < 8; ++nf) {
                float bf[2];
                bf[0] = Vs[(ks * 8 + q) * VP + nf * 8 + g];
                bf[1] = Vs[(ks * 8 + q + 4) * VP + nf * 8 + g];
                mma_tf32(o[nf], pf, bf);
            }
        }
    }

    const float inv0 = 1.0f / l0, inv1 = 1.0f / l1;
    float* ob = ctx + (size_t)(b * SEQ + qt * 64 + wid * 16 + g) * HID + h * HSZ;
#pragma unroll
    for (int nf = 0; nf < 8; ++nf) {
        const int c = nf * 8 + 2 * q;
        float2 v0 = { to_tf32(o[nf][0] * inv0), to_tf32(o[nf][1] * inv0) };
        float2 v1 = { to_tf32(o[nf][2] * inv1), to_tf32(o[nf][3] * inv1) };
        *(float2*)(ob + c) = v0;
        *(float2*)(ob + (size_t)8 * HID + c) = v1;
    }
}

// ===========================================================================
extern "C" void kernel_launch(void* const* d_in, const int* in_sizes, int n_in,
                              void* d_out, int out_size) {
    const float* hs = (const float*)d_in[0];
    const float* w1 = (const float*)d_in[1];
    const float* b1 = (const float*)d_in[2];
    const float* w2 = (const float*)d_in[3];
    const float* b2 = (const float*)d_in[4];
    float* out = (float*)d_out;

    float *qkv, *ctx, *hsr, *w1r, *w2r;
    cudaGetSymbolAddress((void**)&qkv, g_qkv);
    cudaGetSymbolAddress((void**)&ctx, g_ctx);
    cudaGetSymbolAddress((void**)&hsr, g_hs);
    cudaGetSymbolAddress((void**)&w1r, g_w1);
    cudaGetSymbolAddress((void**)&w2r, g_w2);

    cudaFuncSetAttribute((const void*)gemm_tc<128, true, 2>,
                         cudaFuncAttributeMaxDynamicSharedMemorySize,
                         GEMM_SMEM_BM(128));
    cudaFuncSetAttribute((const void*)gemm_tc<64, false, 3>,
                         cudaFuncAttributeMaxDynamicSharedMemorySize,
                         GEMM_SMEM_BM(64));
    cudaFuncSetAttribute((const void*)attn_tc,
                         cudaFuncAttributeMaxDynamicSharedMemorySize, ATTN_SMEM);

    round_all<<<(N4_HS + 255) / 256, 256>>>(
        (const float4*)hs, (float4*)hsr,
        (const float4*)w1, (float4*)w1r,
        (const float4*)w2, (float4*)w2r);

    gemm_tc<128, true, 2><<<dim3(QKV_N / 128, M_TOK / 128), 256,
                            GEMM_SMEM_BM(128)>>>(
        hsr, w1r, b1, qkv, M_TOK, QKV_N, HID);

    attn_tc<<<dim3(SEQ / 64, NHEAD, BATCH), 128, ATTN_SMEM>>>(qkv, ctx);

    gemm_tc<64, false, 3><<<dim3(HID / 128, M_TOK / 64), 256,
                            GEMM_SMEM_BM(64)>>>(
        ctx, w2r, b2, out, M_TOK, HID, HID);
}

// round 15
// speedup vs baseline: 1.0832x; 1.0110x over previous
#include <cuda_runtime.h>
#include <cstdint>

#define BATCH 2
#define SEQ   2048
#define NHEAD 12
#define HSZ   64
#define HID   768
#define M_TOK (BATCH*SEQ)
#define QKV_N (3*HID)

__device__ float g_qkv[M_TOK * QKV_N];
__device__ float g_ctx[M_TOK * HID];
__device__ float g_hs [M_TOK * HID];
__device__ float g_w1 [HID * QKV_N];
__device__ float g_w2 [HID * HID];

// ===========================================================================
__device__ __forceinline__ float to_tf32(float x) {
    uint32_t u;
    asm("cvt.rna.tf32.f32 %0, %1;" : "=r"(u) : "f"(x));
    return __uint_as_float(u);
}
__device__ __forceinline__ float4 cvt4(float4 v) {
    float4 r;
    r.x = to_tf32(v.x); r.y = to_tf32(v.y);
    r.z = to_tf32(v.z); r.w = to_tf32(v.w);
    return r;
}
__device__ __forceinline__ void mma_tf32(float* d, const float* a, const float* b) {
    asm volatile(
        "mma.sync.aligned.m16n8k8.row.col.f32.tf32.tf32.f32 "
        "{%0,%1,%2,%3}, {%4,%5,%6,%7}, {%8,%9}, {%0,%1,%2,%3};"
        : "+f"(d[0]), "+f"(d[1]), "+f"(d[2]), "+f"(d[3])
        : "r"(__float_as_uint(a[0])), "r"(__float_as_uint(a[1])),
          "r"(__float_as_uint(a[2])), "r"(__float_as_uint(a[3])),
          "r"(__float_as_uint(b[0])), "r"(__float_as_uint(b[1])));
}
__device__ __forceinline__ uint32_t smem_u32(const void* p) {
    uint32_t a;
    asm("{ .reg .u64 t; cvta.to.shared.u64 t, %1; cvt.u32.u64 %0, t; }"
        : "=r"(a) : "l"(p));
    return a;
}
__device__ __forceinline__ void cp16(uint32_t dst, const void* src) {
    asm volatile("cp.async.cg.shared.global [%0], [%1], 16;"
                 :: "r"(dst), "l"(src));
}
__device__ __forceinline__ void cp_commit() {
    asm volatile("cp.async.commit_group;" ::: "memory");
}
template<int N> __device__ __forceinline__ void cp_wait() {
    asm volatile("cp.async.wait_group %0;" :: "n"(N) : "memory");
}

// ===========================================================================
// Pre-round all three inputs in one launch
// ===========================================================================
#define N4_HS (M_TOK*HID/4)
#define N4_W1 (HID*QKV_N/4)
#define N4_W2 (HID*HID/4)

__global__ void round_all(const float4* __restrict__ hs, float4* __restrict__ hsr,
                          const float4* __restrict__ w1, float4* __restrict__ w1r,
                          const float4* __restrict__ w2, float4* __restrict__ w2r) {
    int i = blockIdx.x * 256 + threadIdx.x;
    if (i < N4_HS) hsr[i] = cvt4(hs[i]);
    if (i < N4_W1) w1r[i] = cvt4(w1[i]);
    if (i < N4_W2) w2r[i] = cvt4(w2[i]);
}

// ===========================================================================
// GEMM: BMx128 block, 8 warps (2x4), warp tile (BM/2)x32, BK-deep stages,
// 3-stage cp.async, one barrier per stage.
// ===========================================================================
#define BPIT 136

template<int BM, int BK, bool ROUND_OUT, int MINB>
__global__ void __launch_bounds__(256, MINB)
gemm_tc(const float* __restrict__ A, const float* __restrict__ B,
        const float* __restrict__ bias, float* __restrict__ C,
        int M, int N, int K) {
    constexpr int APIT = BK + 4;
    constexpr int ASTG = BM * APIT;
    constexpr int BSTG = BK * BPIT;
    constexpr int STG  = ASTG + BSTG;
    constexpr int MF   = BM / 32;
    constexpr int ACH  = BM * BK / 1024;   // A cp16 per thread
    constexpr int BCH  = BK * 128 / 1024;  // B cp16 per thread
    constexpr int CPR  = BK / 4;           // A chunks per row

    extern __shared__ float sm[];
    const uint32_t smb = smem_u32(sm);

    const int tid = threadIdx.x, lane = tid & 31, wid = tid >> 5;
    const int g = lane >> 2, q = lane & 3;
    const int wm = wid >> 2, wn = wid & 3;
    const int bm = blockIdx.y * BM, bn = blockIdx.x * 128;
    const int nst = K / BK;

    auto prefetch = [&](int S) {
        const int k0 = S * BK;
        const uint32_t bs = smb + (S % 3) * (STG * 4);
#pragma unroll
        for (int r = 0; r < ACH; ++r) {
            const int c = tid + 256 * r;
            const int row = c / CPR, kc = c % CPR;
            cp16(bs + (row * APIT + kc * 4) * 4,
                 A + (size_t)(bm + row) * K + k0 + kc * 4);
        }
#pragma unroll
        for (int r = 0; r < BCH; ++r) {
            const int c = tid + 256 * r;
            const int row = c >> 5, nc = c & 31;
            cp16(bs + (ASTG + row * BPIT + nc * 4) * 4,
                 B + (size_t)(k0 + row) * N + bn + nc * 4);
        }
    };

    float acc[MF][4][4];
#pragma unroll
    for (int mf = 0; mf < MF; ++mf)
#pragma unroll
        for (int nf = 0; nf < 4; ++nf)
#pragma unroll
            for (int e = 0; e < 4; ++e) acc[mf][nf][e] = 0.f;

    prefetch(0); cp_commit();
    prefetch(1); cp_commit();

    for (int s = 0; s < nst; ++s) {
        if (s + 1 < nst) cp_wait<1>(); else cp_wait<0>();
        __syncthreads();
        if (s + 2 < nst) { prefetch(s + 2); cp_commit(); }

        const float* a  = sm + (s % 3) * STG;
        const float* bb = a + ASTG;
#pragma unroll
        for (int ks = 0; ks < BK / 8; ++ks) {
            const int k0 = ks * 8;
            float af[MF][4];
#pragma unroll
            for (int mf = 0; mf < MF; ++mf) {
                const int r0 = (wm * (BM / 2) + mf * 16 + g) * APIT + k0 + q;
                af[mf][0] = a[r0];
                af[mf][1] = a[r0 + 8 * APIT];
                af[mf][2] = a[r0 + 4];
                af[mf][3] = a[r0 + 8 * APIT + 4];
            }
#pragma unroll
            for (int nf = 0; nf < 4; ++nf) {
                float bf[2];
                const int c = wn * 32 + nf * 8 + g;
                bf[0] = bb[(k0 + q) * BPIT + c];
                bf[1] = bb[(k0 + q + 4) * BPIT + c];
#pragma unroll
                for (int mf = 0; mf < MF; ++mf)
                    mma_tf32(acc[mf][nf], af[mf], bf);
            }
        }
    }

#pragma unroll
    for (int mf = 0; mf < MF; ++mf) {
        const int row = bm + wm * (BM / 2) + mf * 16 + g;
#pragma unroll
        for (int nf = 0; nf < 4; ++nf) {
            const int col = bn + wn * 32 + nf * 8 + 2 * q;
            float2 bv = *(const float2*)(bias + col);
            float2 v0 = { acc[mf][nf][0] + bv.x, acc[mf][nf][1] + bv.y };
            float2 v1 = { acc[mf][nf][2] + bv.x, acc[mf][nf][3] + bv.y };
            if (ROUND_OUT) {
                v0.x = to_tf32(v0.x); v0.y = to_tf32(v0.y);
                v1.x = to_tf32(v1.x); v1.y = to_tf32(v1.y);
            }
            *(float2*)(C + (size_t)row * N + col) = v0;
            *(float2*)(C + (size_t)(row + 8) * N + col) = v1;
        }
    }
}

#define GEMM_SMEM(BM, BK) (3 * ((BM) * ((BK) + 4) + (BK) * BPIT) * 4)

// ===========================================================================
// Attention: R12 version verbatim (best measured). FROZEN.
// ===========================================================================
#define KP 68
#define VP 72
#define KSTG (64*KP)
#define VSTG (64*VP)
#define PQ_OFF (2*KSTG + 2*VSTG)
#define ATTN_SMEM ((PQ_OFF + 4352)*4)   // 89088 B

__global__ void __launch_bounds__(128)
attn_tc(const float* __restrict__ qkv, float* __restrict__ ctx) {
    const int qt = blockIdx.x, h = blockIdx.y, b = blockIdx.z;
    const int tid = threadIdx.x, lane = tid & 31, wid = tid >> 5;
    const int g = lane >> 2, q = lane & 3;

    extern __shared__ float sms[];
    const uint32_t smb = smem_u32(sms);
    float* PQ = sms + PQ_OFF;
    float* Pw = PQ + wid * 16 * KP;

#define KV_PREFETCH(KT, P)                                                      \
    do {                                                                        \
        const float* _kb = qkv + (size_t)(b * SEQ + (KT) * 64) * QKV_N          \
                           + HID + h * HSZ;                                     \
        const uint32_t _kbs = smb + (P) * (KSTG * 4);                           \
        const uint32_t _vbs = smb + (2 * KSTG + (P) * VSTG) * 4;                \
        _Pragma("unroll")                                                       \
        for (int _r = 0; _r < 8; ++_r) {                                        \
            const int _c = tid + 128 * _r;                                      \
            const int _row = _c >> 4, _kc = _c & 15;                            \
            cp16(_kbs + (_row * KP + _kc * 4) * 4,                              \
                 _kb + (size_t)_row * QKV_N + _kc * 4);                         \
            cp16(_vbs + (_row * VP + _kc * 4) * 4,                              \
                 _kb + HID + (size_t)_row * QKV_N + _kc * 4);                   \
        }                                                                       \
    } while (0)

    {
        const float* qb = qkv + (size_t)(b * SEQ + qt * 64) * QKV_N + h * HSZ;
        const uint32_t pqb = smb + PQ_OFF * 4;
#pragma unroll
        for (int r = 0; r < 8; ++r) {
            const int c = tid + 128 * r;
            const int row = c >> 4, kc = c & 15;
            cp16(pqb + (row * KP + kc * 4) * 4, qb + (size_t)row * QKV_N + kc * 4);
        }
        cp_commit();
    }
    KV_PREFETCH(0, 0); cp_commit();
    cp_wait<1>();
    __syncthreads();

    float qa[8][4];
#pragma unroll
    for (int ks = 0; ks < 8; ++ks) {
        const int r0 = (wid * 16 + g) * KP + ks * 8 + q;
        qa[ks][0] = PQ[r0] * 0.125f;
        qa[ks][1] = PQ[r0 + 8 * KP] * 0.125f;
        qa[ks][2] = PQ[r0 + 4] * 0.125f;
        qa[ks][3] = PQ[r0 + 8 * KP + 4] * 0.125f;
    }

    float o[8][4];
#pragma unroll
    for (int nf = 0; nf < 8; ++nf)
#pragma unroll
        for (int e = 0; e < 4; ++e) o[nf][e] = 0.f;
    float m0 = -1e30f, m1 = -1e30f, l0 = 0.f, l1 = 0.f;

    for (int kt = 0; kt <= qt; ++kt) {
        const int p = kt & 1;
        cp_wait<0>();
        __syncthreads();
        if (kt < qt) {
            KV_PREFETCH(kt + 1, 1 - p);
            cp_commit();
        }

        const float* Ks = sms + p * KSTG;
        const float* Vs = sms + 2 * KSTG + p * VSTG;
        const int nlim = (kt == qt) ? (2 * wid + 2) : 8;

        float s[8][4];
        for (int nf = 0; nf < nlim; ++nf) {
            s[nf][0] = 0.f; s[nf][1] = 0.f; s[nf][2] = 0.f; s[nf][3] = 0.f;
            const int nrow = (nf * 8 + g) * KP;
#pragma unroll
            for (int ks = 0; ks < 8; ++ks) {
                float bf[2];
                bf[0] = Ks[nrow + ks * 8 + q];
                bf[1] = Ks[nrow + ks * 8 + q + 4];
                mma_tf32(s[nf], qa[ks], bf);
            }
        }

        if (kt == qt) {
            const int q0 = wid * 16 + g;
            for (int nf = 0; nf < nlim; ++nf) {
                const int key = nf * 8 + 2 * q;
                if (key     > q0)     s[nf][0] = -1e30f;
                if (key + 1 > q0)     s[nf][1] = -1e30f;
                if (key     > q0 + 8) s[nf][2] = -1e30f;
                if (key + 1 > q0 + 8) s[nf][3] = -1e30f;
            }
        }

        float mx0 = -1e30f, mx1 = -1e30f;
        for (int nf = 0; nf < nlim; ++nf) {
            mx0 = fmaxf(mx0, fmaxf(s[nf][0], s[nf][1]));
            mx1 = fmaxf(mx1, fmaxf(s[nf][2], s[nf][3]));
        }
        mx0 = fmaxf(mx0, __shfl_xor_sync(0xffffffffu, mx0, 1));
        mx0 = fmaxf(mx0, __shfl_xor_sync(0xffffffffu, mx0, 2));
        mx1 = fmaxf(mx1, __shfl_xor_sync(0xffffffffu, mx1, 1));
        mx1 = fmaxf(mx1, __shfl_xor_sync(0xffffffffu, mx1, 2));
        const float mn0 = fmaxf(m0, mx0), mn1 = fmaxf(m1, mx1);
        const float a0 = __expf(m0 - mn0), a1 = __expf(m1 - mn1);
        m0 = mn0; m1 = mn1;

        float sum0 = 0.f, sum1 = 0.f;
        for (int nf = 0; nf < nlim; ++nf) {
            s[nf][0] = __expf(s[nf][0] - mn0);
            s[nf][1] = __expf(s[nf][1] - mn0);
            s[nf][2] = __expf(s[nf][2] - mn1);
            s[nf][3] = __expf(s[nf][3] - mn1);
            sum0 += s[nf][0] + s[nf][1];
            sum1 += s[nf][2] + s[nf][3];
        }
        sum0 += __shfl_xor_sync(0xffffffffu, sum0, 1);
        sum0 += __shfl_xor_sync(0xffffffffu, sum0, 2);
        sum1 += __shfl_xor_sync(0xffffffffu, sum1, 1);
        sum1 += __shfl_xor_sync(0xffffffffu, sum1, 2);
        l0 = l0 * a0 + sum0;
        l1 = l1 * a1 + sum1;
#pragma unroll
        for (int nf = 0; nf < 8; ++nf) {
            o[nf][0] *= a0; o[nf][1] *= a0;
            o[nf][2] *= a1; o[nf][3] *= a1;
        }

        __syncwarp();
        for (int nf = 0; nf < nlim; ++nf) {
            const int c = nf * 8 + 2 * q;
            float2 w0 = { to_tf32(s[nf][0]), to_tf32(s[nf][1]) };
            float2 w1 = { to_tf32(s[nf][2]), to_tf32(s[nf][3]) };
            *(float2*)&Pw[g * KP + c] = w0;
            *(float2*)&Pw[(g + 8) * KP + c] = w1;
        }
        __syncwarp();

        for (int ks = 0; ks < nlim; ++ks) {
            float pf[4];
            const int pr = g * KP + ks * 8 + q;
            pf[0] = Pw[pr];
            pf[1] = Pw[pr + 8 * KP];
            pf[2] = Pw[pr + 4];
            pf[3] = Pw[pr + 8 * KP + 4];
#pragma unroll
            for (int nf = 0; nf < 8; ++nf) {
                float bf[2];
                bf[0] = Vs[(ks * 8 + q) * VP + nf * 8 + g];
                bf[1] = Vs[(ks * 8 + q + 4) * VP + nf * 8 + g];
                mma_tf32(o[nf], pf, bf);
            }
        }
    }

    const float inv0 = 1.0f / l0, inv1 = 1.0f / l1;
    float* ob = ctx + (size_t)(b * SEQ + qt * 64 + wid * 16 + g) * HID + h * HSZ;
#pragma unroll
    for (int nf = 0; nf < 8; ++nf) {
        const int c = nf * 8 + 2 * q;
        float2 v0 = { to_tf32(o[nf][0] * inv0), to_tf32(o[nf][1] * inv0) };
        float2 v1 = { to_tf32(o[nf][2] * inv1), to_tf32(o[nf][3] * inv1) };
        *(float2*)(ob + c) = v0;
        *(float2*)(ob + (size_t)8 * HID + c) = v1;
    }
}

// ===========================================================================
extern "C" void kernel_launch(void* const* d_in, const int* in_sizes, int n_in,
                              void* d_out, int out_size) {
    const float* hs = (const float*)d_in[0];
    const float* w1 = (const float*)d_in[1];
    const float* b1 = (const float*)d_in[2];
    const float* w2 = (const float*)d_in[3];
    const float* b2 = (const float*)d_in[4];
    float* out = (float*)d_out;

    float *qkv, *ctx, *hsr, *w1r, *w2r;
    cudaGetSymbolAddress((void**)&qkv, g_qkv);
    cudaGetSymbolAddress((void**)&ctx, g_ctx);
    cudaGetSymbolAddress((void**)&hsr, g_hs);
    cudaGetSymbolAddress((void**)&w1r, g_w1);
    cudaGetSymbolAddress((void**)&w2r, g_w2);

    cudaFuncSetAttribute((const void*)gemm_tc<128, 32, true, 2>,
                         cudaFuncAttributeMaxDynamicSharedMemorySize,
                         GEMM_SMEM(128, 32));
    cudaFuncSetAttribute((const void*)gemm_tc<64, 16, false, 3>,
                         cudaFuncAttributeMaxDynamicSharedMemorySize,
                         GEMM_SMEM(64, 16));
    cudaFuncSetAttribute((const void*)attn_tc,
                         cudaFuncAttributeMaxDynamicSharedMemorySize, ATTN_SMEM);

    round_all<<<(N4_HS + 255) / 256, 256>>>(
        (const float4*)hs, (float4*)hsr,
        (const float4*)w1, (float4*)w1r,
        (const float4*)w2, (float4*)w2r);

    // QKV: BK=32, half the barriers
    gemm_tc<128, 32, true, 2><<<dim3(QKV_N / 128, M_TOK / 128), 256,
                                GEMM_SMEM(128, 32)>>>(
        hsr, w1r, b1, qkv, M_TOK, QKV_N, HID);

    attn_tc<<<dim3(SEQ / 64, NHEAD, BATCH), 128, ATTN_SMEM>>>(qkv, ctx);

    // proj: measured-best config (BM=64, BK=16, 3 CTAs/SM)
    gemm_tc<64, 16, false, 3><<<dim3(HID / 128, M_TOK / 64), 256,
                                GEMM_SMEM(64, 16)>>>(
        ctx, w2r, b2, out, M_TOK, HID, HID);
}